// round 2
// baseline (speedup 1.0000x reference)
#include <cuda_runtime.h>
#include <cstdint>
#include <cstddef>

// GhostLinear: out[b,s,o] = sum_i x[b,s,i] * (lut[grid_indices[o,i]] * scale[o])
// M = 8192 (B*S), N = 4096 (out_f), K = 4096 (in_f), fp32.
// Arch constraint (observed R1): harness compiles at compute_103 (no 'a'),
// so tcgen05/TMEM are unavailable. Use legacy mma.sync tf32 (sm_80+ path).
//
// Stage 1: dequant W = round_tf32(lut[gi] * scale) into __device__ scratch.
// Stage 2: pipelined GEMM, BM=BN=128, BK=32, 4-stage cp.async, mma.m16n8k8.tf32.

#define M_DIM 8192
#define N_DIM 4096
#define K_DIM 4096

#define BM 128
#define BN 128
#define BK 32
#define NSTAGES 4
#define NK (K_DIM / BK)          // 128 K-chunks

#define PITCH 36                  // floats per smem row (144 B: 16B-aligned, conflict-free)
#define TILE_BYTES (128 * PITCH * 4)      // 18432
#define STAGE_BYTES (2 * TILE_BYTES)      // A + B = 36864
#define SMEM_DYN (NSTAGES * STAGE_BYTES)  // 147456

// 64 MB dequantized-weight scratch (device global: allocation-free).
__device__ float g_W[(size_t)N_DIM * (size_t)K_DIM];

__device__ __forceinline__ uint32_t smem_u32(const void* p) {
    uint32_t a;
    asm("{ .reg .u64 t; cvta.to.shared.u64 t, %1; cvt.u32.u64 %0, t; }"
        : "=r"(a) : "l"(p));
    return a;
}

#define CP_ASYNC16(smem, gmem) \
    asm volatile("cp.async.cg.shared.global [%0], [%1], 16;" :: "r"(smem), "l"(gmem) : "memory")
#define CP_COMMIT() asm volatile("cp.async.commit_group;" ::: "memory")
#define CP_WAIT(n)  asm volatile("cp.async.wait_group %0;" :: "n"(n) : "memory")

__device__ __forceinline__ uint32_t f2tf32(float f) {
    uint32_t u;
    asm("cvt.rna.tf32.f32 %0, %1;" : "=r"(u) : "f"(f));
    return u;
}

__device__ __forceinline__ void mma_tf32(float& c0, float& c1, float& c2, float& c3,
                                         uint32_t a0, uint32_t a1, uint32_t a2, uint32_t a3,
                                         uint32_t b0, uint32_t b1) {
    asm volatile(
        "mma.sync.aligned.m16n8k8.row.col.f32.tf32.tf32.f32 "
        "{%0,%1,%2,%3}, {%4,%5,%6,%7}, {%8,%9}, {%0,%1,%2,%3};"
        : "+f"(c0), "+f"(c1), "+f"(c2), "+f"(c3)
        : "r"(a0), "r"(a1), "r"(a2), "r"(a3), "r"(b0), "r"(b1));
}

// ---------------------------------------------------------------------------
// Stage 1: dequant W = tf32_round(lut[grid_indices] * scale)
// ---------------------------------------------------------------------------
__global__ void __launch_bounds__(256) ghost_dequant(const int4* __restrict__ gi,
                                                     const float* __restrict__ lut,
                                                     const float* __restrict__ scale) {
    unsigned i = blockIdx.x * 256u + threadIdx.x;   // float4 index, 0..4194303
    int4 v = gi[i];
    float s = __ldg(&scale[i >> 10]);               // 1024 float4 per 4096-wide row
    uint4 w;
    w.x = f2tf32(__ldg(&lut[v.x]) * s);
    w.y = f2tf32(__ldg(&lut[v.y]) * s);
    w.z = f2tf32(__ldg(&lut[v.z]) * s);
    w.w = f2tf32(__ldg(&lut[v.w]) * s);
    reinterpret_cast<uint4*>(g_W)[i] = w;
}

// ---------------------------------------------------------------------------
// Stage 2: GEMM  Out[M,N] = X[M,K] * W[N,K]^T
// 256 threads = 8 warps (2 m x 4 n), warp tile 64x32, mma m16n8k8 tf32.
// ---------------------------------------------------------------------------
__global__ void __launch_bounds__(256, 1) ghost_gemm(const float* __restrict__ X,
                                                     float* __restrict__ Out) {
    extern __shared__ char dynsmem[];
    float* sm = (float*)dynsmem;

    const int tid = threadIdx.x;
    const int lane = tid & 31;
    const int wid = tid >> 5;
    const int wm = wid >> 2;          // 0..1  (64-row slab)
    const int wn = wid & 3;           // 0..3  (32-col slab)
    const int g = lane >> 2;          // 0..7  fragment row group
    const int t = lane & 3;           // 0..3  fragment k/col id

    const int n0 = blockIdx.x * BN;
    const int m0 = blockIdx.y * BM;

    const uint32_t sbase = smem_u32(sm);

    // ---- cp.async geometry: 8 chunks (16B) per thread per stage per tile ----
    const int part = tid & 7;         // 16B chunk within 128B row
    const int row4 = tid >> 3;        // base row, +32 per j
    const float* gA[4];
    const float* gB[4];
    uint32_t sOff[4];
    #pragma unroll
    for (int j = 0; j < 4; j++) {
        int row = j * 32 + row4;
        sOff[j] = (uint32_t)(row * PITCH * 4 + part * 16);
        gA[j] = X + (size_t)(m0 + row) * K_DIM + part * 4;
        gB[j] = g_W + (size_t)(n0 + row) * K_DIM + part * 4;
    }

    // ---- prologue: fill NSTAGES-1 stages ----
    #pragma unroll
    for (int c = 0; c < NSTAGES - 1; c++) {
        uint32_t ab = sbase + c * STAGE_BYTES;
        uint32_t bb = ab + TILE_BYTES;
        int koff = c * BK;
        #pragma unroll
        for (int j = 0; j < 4; j++) CP_ASYNC16(ab + sOff[j], gA[j] + koff);
        #pragma unroll
        for (int j = 0; j < 4; j++) CP_ASYNC16(bb + sOff[j], gB[j] + koff);
        CP_COMMIT();
    }

    float acc[4][4][4];
    #pragma unroll
    for (int i = 0; i < 4; i++)
        #pragma unroll
        for (int j = 0; j < 4; j++)
            #pragma unroll
            for (int q = 0; q < 4; q++) acc[i][j][q] = 0.0f;

    // Per-thread fragment smem word offsets (bytes), conflict-free with PITCH=36.
    // A: rows wm*64 + mt*16 + g (+8), cols k + t (+4)
    // B: rows wn*32 + nt*8 + g,       cols k + t (+4)
    const uint32_t aRow = (uint32_t)(wm * 64 + g);
    const uint32_t bRow = (uint32_t)(wn * 32 + g);

    for (int kt = 0; kt < NK; kt++) {
        if (kt < NK - 3) CP_WAIT(2);
        else             CP_WAIT(0);
        __syncthreads();

        const uint32_t aBase = sbase + (kt % NSTAGES) * STAGE_BYTES;
        const uint32_t bBase = aBase + TILE_BYTES;

        #pragma unroll
        for (int ks = 0; ks < 4; ks++) {
            const uint32_t kb = (uint32_t)(ks * 8 + t) * 4;   // byte offset of k+t

            uint32_t a[4][4];
            #pragma unroll
            for (int mt = 0; mt < 4; mt++) {
                uint32_t base = aBase + (aRow + mt * 16) * (PITCH * 4) + kb;
                float f0, f1, f2, f3;
                asm volatile("ld.shared.f32 %0, [%1];" : "=f"(f0) : "r"(base));
                asm volatile("ld.shared.f32 %0, [%1];" : "=f"(f1) : "r"(base + 8 * PITCH * 4));
                asm volatile("ld.shared.f32 %0, [%1];" : "=f"(f2) : "r"(base + 16));
                asm volatile("ld.shared.f32 %0, [%1];" : "=f"(f3) : "r"(base + 8 * PITCH * 4 + 16));
                a[mt][0] = f2tf32(f0); a[mt][1] = f2tf32(f1);
                a[mt][2] = f2tf32(f2); a[mt][3] = f2tf32(f3);
            }

            uint32_t b[4][2];
            #pragma unroll
            for (int nt = 0; nt < 4; nt++) {
                uint32_t base = bBase + (bRow + nt * 8) * (PITCH * 4) + kb;
                asm volatile("ld.shared.b32 %0, [%1];" : "=r"(b[nt][0]) : "r"(base));
                asm volatile("ld.shared.b32 %0, [%1];" : "=r"(b[nt][1]) : "r"(base + 16));
            }

            #pragma unroll
            for (int mt = 0; mt < 4; mt++)
                #pragma unroll
                for (int nt = 0; nt < 4; nt++)
                    mma_tf32(acc[mt][nt][0], acc[mt][nt][1], acc[mt][nt][2], acc[mt][nt][3],
                             a[mt][0], a[mt][1], a[mt][2], a[mt][3],
                             b[nt][0], b[nt][1]);
        }

        __syncthreads();

        const int kc = kt + (NSTAGES - 1);
        if (kc < NK) {
            uint32_t ab = sbase + (kc % NSTAGES) * STAGE_BYTES;
            uint32_t bb = ab + TILE_BYTES;
            int koff = kc * BK;
            #pragma unroll
            for (int j = 0; j < 4; j++) CP_ASYNC16(ab + sOff[j], gA[j] + koff);
            #pragma unroll
            for (int j = 0; j < 4; j++) CP_ASYNC16(bb + sOff[j], gB[j] + koff);
            CP_COMMIT();
        }
    }

    // ---- epilogue: direct float2 stores ----
    // c0,c1 -> (row, 2t), (row, 2t+1); c2,c3 -> row+8.
    #pragma unroll
    for (int mt = 0; mt < 4; mt++) {
        int rbase = m0 + wm * 64 + mt * 16 + g;
        #pragma unroll
        for (int nt = 0; nt < 4; nt++) {
            int col = n0 + wn * 32 + nt * 8 + 2 * t;
            float2 v0 = make_float2(acc[mt][nt][0], acc[mt][nt][1]);
            float2 v1 = make_float2(acc[mt][nt][2], acc[mt][nt][3]);
            *(float2*)(Out + (size_t)rbase * N_DIM + col) = v0;
            *(float2*)(Out + (size_t)(rbase + 8) * N_DIM + col) = v1;
        }
    }
}

// ---------------------------------------------------------------------------
// Launch
// ---------------------------------------------------------------------------
extern "C" void kernel_launch(void* const* d_in, const int* in_sizes, int n_in,
                              void* d_out, int out_size) {
    const float* x   = (const float*)d_in[0];   // [4, 2048, 4096] f32
    const int*   gi  = (const int*)d_in[1];     // [4096, 4096] i32
    const float* lut = (const float*)d_in[2];   // [65536] f32
    const float* sc  = (const float*)d_in[3];   // [4096, 1] f32
    float* out = (float*)d_out;                 // [4, 2048, 4096] f32

    (void)in_sizes; (void)n_in; (void)out_size;

    ghost_dequant<<<(N_DIM * K_DIM / 4) / 256, 256>>>((const int4*)gi, lut, sc);

    cudaFuncSetAttribute(ghost_gemm, cudaFuncAttributeMaxDynamicSharedMemorySize, SMEM_DYN);
    ghost_gemm<<<dim3(N_DIM / BN, M_DIM / BM), 256, SMEM_DYN>>>(x, out);
}

// round 3
// speedup vs baseline: 3.5012x; 3.5012x over previous
#include <cuda_runtime.h>
#include <cuda_fp16.h>
#include <cstdint>
#include <cstddef>

// GhostLinear: out = x @ (lut[gi]*scale)^T.  M=8192, N=4096, K=4096.
// R3: fp16 inputs (same 10-bit mantissa as tf32), fp32 accum, mma.m16n8k16,
// ldmatrix fragment loads, 4-stage cp.async, 2 CTAs/SM.

#define M_DIM 8192
#define N_DIM 4096
#define K_DIM 4096

#define BM 128
#define BN 128
#define BK 32
#define NSTAGES 4
#define NK (K_DIM / BK)                 // 128

#define TILE_BYTES (128 * 64)           // 128 rows x 32 halfs (64B)
#define STAGE_BYTES (2 * TILE_BYTES)    // A + B = 16384
#define SMEM_DYN (NSTAGES * STAGE_BYTES)  // 65536

// Scratch (device globals: allocation-free): W fp16 (32MB) + X fp16 (64MB)
__device__ __half g_Wh[(size_t)N_DIM * (size_t)K_DIM];
__device__ __half g_Xh[(size_t)M_DIM * (size_t)K_DIM];

__device__ __forceinline__ uint32_t smem_u32(const void* p) {
    uint32_t a;
    asm("{ .reg .u64 t; cvta.to.shared.u64 t, %1; cvt.u32.u64 %0, t; }"
        : "=r"(a) : "l"(p));
    return a;
}

#define CP_ASYNC16(smem, gmem) \
    asm volatile("cp.async.cg.shared.global [%0], [%1], 16;" :: "r"(smem), "l"(gmem) : "memory")
#define CP_COMMIT() asm volatile("cp.async.commit_group;" ::: "memory")
#define CP_WAIT(n)  asm volatile("cp.async.wait_group %0;" :: "n"(n) : "memory")

#define LDSM_X4(r0, r1, r2, r3, addr) \
    asm volatile("ldmatrix.sync.aligned.m8n8.x4.shared.b16 {%0,%1,%2,%3}, [%4];" \
                 : "=r"(r0), "=r"(r1), "=r"(r2), "=r"(r3) : "r"(addr))

__device__ __forceinline__ void mma_f16(float& c0, float& c1, float& c2, float& c3,
                                        uint32_t a0, uint32_t a1, uint32_t a2, uint32_t a3,
                                        uint32_t b0, uint32_t b1) {
    asm volatile(
        "mma.sync.aligned.m16n8k16.row.col.f32.f16.f16.f32 "
        "{%0,%1,%2,%3}, {%4,%5,%6,%7}, {%8,%9}, {%0,%1,%2,%3};"
        : "+f"(c0), "+f"(c1), "+f"(c2), "+f"(c3)
        : "r"(a0), "r"(a1), "r"(a2), "r"(a3), "r"(b0), "r"(b1));
}

// ---------------------------------------------------------------------------
// Prep kernels
// ---------------------------------------------------------------------------
// W = half(lut[gi] * scale): 8 elements/thread.
__global__ void __launch_bounds__(256) ghost_dequant(const int4* __restrict__ gi,
                                                     const float* __restrict__ lut,
                                                     const float* __restrict__ scale) {
    unsigned i = blockIdx.x * 256u + threadIdx.x;      // 8-pack index (2,097,152 total)
    int4 v0 = gi[2 * i];
    int4 v1 = gi[2 * i + 1];
    float s = __ldg(&scale[i >> 9]);                   // 512 packs per 4096-wide row
    __half2 h0 = __floats2half2_rn(__ldg(&lut[v0.x]) * s, __ldg(&lut[v0.y]) * s);
    __half2 h1 = __floats2half2_rn(__ldg(&lut[v0.z]) * s, __ldg(&lut[v0.w]) * s);
    __half2 h2 = __floats2half2_rn(__ldg(&lut[v1.x]) * s, __ldg(&lut[v1.y]) * s);
    __half2 h3 = __floats2half2_rn(__ldg(&lut[v1.z]) * s, __ldg(&lut[v1.w]) * s);
    uint4 w;
    w.x = *(uint32_t*)&h0; w.y = *(uint32_t*)&h1;
    w.z = *(uint32_t*)&h2; w.w = *(uint32_t*)&h3;
    reinterpret_cast<uint4*>(g_Wh)[i] = w;
}

// X -> fp16: 8 elements/thread.
__global__ void __launch_bounds__(256) ghost_xconv(const float4* __restrict__ X) {
    unsigned i = blockIdx.x * 256u + threadIdx.x;      // 8-pack index (4,194,304 total)
    float4 f0 = X[2 * i];
    float4 f1 = X[2 * i + 1];
    __half2 h0 = __floats2half2_rn(f0.x, f0.y);
    __half2 h1 = __floats2half2_rn(f0.z, f0.w);
    __half2 h2 = __floats2half2_rn(f1.x, f1.y);
    __half2 h3 = __floats2half2_rn(f1.z, f1.w);
    uint4 w;
    w.x = *(uint32_t*)&h0; w.y = *(uint32_t*)&h1;
    w.z = *(uint32_t*)&h2; w.w = *(uint32_t*)&h3;
    reinterpret_cast<uint4*>(g_Xh)[i] = w;
}

// ---------------------------------------------------------------------------
// GEMM: Out[M,N] = Xh[M,K] * Wh[N,K]^T
// 256 threads = 8 warps (2m x 4n), warp tile 64x32, mma m16n8k16 f16->f32.
// smem row = 32 halfs (64B, 4 x 16B chunks); swizzle: chunk ^= (row>>1)&3.
// ---------------------------------------------------------------------------
__global__ void __launch_bounds__(256, 2) ghost_gemm(float* __restrict__ Out) {
    extern __shared__ char dynsmem[];

    const int tid = threadIdx.x;
    const int lane = tid & 31;
    const int wid = tid >> 5;
    const int wm = wid >> 2;              // 0..1
    const int wn = wid & 3;               // 0..3
    const int g = lane >> 2;              // 0..7
    const int t = lane & 3;               // 0..3

    const int n0 = blockIdx.x * BN;
    const int m0 = blockIdx.y * BM;

    const uint32_t sbase = smem_u32(dynsmem);

    // ---- cp.async geometry: 2 chunks (16B) per thread per tile per stage ----
    // chunk id cid = tid*2 + j ; row = cid>>2 ; chunk = cid&3
    const int cprow = tid >> 1;                       // 0..127
    const int cpc0 = (tid & 1) * 2;                   // chunk 0 or 2
    const uint32_t cpsx = (uint32_t)((cprow >> 1) & 3);
    uint32_t cpOff[2];
    cpOff[0] = (uint32_t)(cprow * 64 + ((cpc0 ^ cpsx) << 4));
    cpOff[1] = (uint32_t)(cprow * 64 + (((cpc0 + 1) ^ cpsx) << 4));
    const __half* gA = g_Xh + (size_t)(m0 + cprow) * K_DIM + cpc0 * 8;
    const __half* gB = g_Wh + (size_t)(n0 + cprow) * K_DIM + cpc0 * 8;

    // ---- prologue ----
    #pragma unroll
    for (int c = 0; c < NSTAGES - 1; c++) {
        uint32_t ab = sbase + c * STAGE_BYTES;
        uint32_t bb = ab + TILE_BYTES;
        int koff = c * BK;
        CP_ASYNC16(ab + cpOff[0], gA + koff);
        CP_ASYNC16(ab + cpOff[1], gA + koff + 8);
        CP_ASYNC16(bb + cpOff[0], gB + koff);
        CP_ASYNC16(bb + cpOff[1], gB + koff + 8);
        CP_COMMIT();
    }

    // ---- ldmatrix per-thread address pieces ----
    const int q = lane >> 3;              // matrix slot 0..3
    const int r = lane & 7;               // row within matrix
    const uint32_t sx = (uint32_t)((r >> 1) & 3);   // swizzle key (row bits 1..2 == r bits 1..2)
    // A: matrices (mt tile): M0 rows+0..7 k0-7, M1 rows+8..15 k0-7, M2 +0..7 k8-15, M3 +8..15 k8-15
    const uint32_t aRowBase = (uint32_t)(wm * 64 + (q & 1) * 8 + r) * 64;
    const uint32_t aChunkQ = (uint32_t)(q >> 1);
    // B: matrices (nt2 pair): M0 n+0..7 k0-7, M1 n+0..7 k8-15, M2 n+8..15 k0-7, M3 n+8..15 k8-15
    const uint32_t bRowBase = (uint32_t)(wn * 32 + (q >> 1) * 8 + r) * 64;
    const uint32_t bChunkQ = (uint32_t)(q & 1);

    float acc[4][4][4];
    #pragma unroll
    for (int i = 0; i < 4; i++)
        #pragma unroll
        for (int j = 0; j < 4; j++)
            #pragma unroll
            for (int k2 = 0; k2 < 4; k2++) acc[i][j][k2] = 0.0f;

    for (int kt = 0; kt < NK; kt++) {
        if (kt < NK - (NSTAGES - 1)) CP_WAIT(2);
        else                         CP_WAIT(0);
        __syncthreads();

        // prefetch next stage (reuses the stage finished last iteration)
        const int kc = kt + (NSTAGES - 1);
        if (kc < NK) {
            uint32_t ab = sbase + (kc % NSTAGES) * STAGE_BYTES;
            uint32_t bb = ab + TILE_BYTES;
            int koff = kc * BK;
            CP_ASYNC16(ab + cpOff[0], gA + koff);
            CP_ASYNC16(ab + cpOff[1], gA + koff + 8);
            CP_ASYNC16(bb + cpOff[0], gB + koff);
            CP_ASYNC16(bb + cpOff[1], gB + koff + 8);
            CP_COMMIT();
        }

        const uint32_t aTile = sbase + (kt % NSTAGES) * STAGE_BYTES;
        const uint32_t bTile = aTile + TILE_BYTES;

        #pragma unroll
        for (int ks = 0; ks < 2; ks++) {              // two k16 steps per BK=32
            const uint32_t cA = ((uint32_t)(ks * 2) + aChunkQ) ^ sx;
            const uint32_t cB = ((uint32_t)(ks * 2) + bChunkQ) ^ sx;

            uint32_t a[4][4];
            #pragma unroll
            for (int mt = 0; mt < 4; mt++) {
                uint32_t addr = aTile + aRowBase + (uint32_t)(mt * 1024) + (cA << 4);
                LDSM_X4(a[mt][0], a[mt][1], a[mt][2], a[mt][3], addr);
            }
            uint32_t b[2][4];
            #pragma unroll
            for (int nt2 = 0; nt2 < 2; nt2++) {
                uint32_t addr = bTile + bRowBase + (uint32_t)(nt2 * 1024) + (cB << 4);
                LDSM_X4(b[nt2][0], b[nt2][1], b[nt2][2], b[nt2][3], addr);
            }

            #pragma unroll
            for (int mt = 0; mt < 4; mt++) {
                #pragma unroll
                for (int nt = 0; nt < 4; nt++) {
                    // nt -> (nt2 = nt>>1, hi/lo = nt&1): b-regs (b0,b1) = ([2*(nt&1)], [2*(nt&1)+1])
                    mma_f16(acc[mt][nt][0], acc[mt][nt][1], acc[mt][nt][2], acc[mt][nt][3],
                            a[mt][0], a[mt][1], a[mt][2], a[mt][3],
                            b[nt >> 1][2 * (nt & 1)], b[nt >> 1][2 * (nt & 1) + 1]);
                }
            }
        }
    }

    // ---- epilogue: direct float2 stores (c0,c1 at row g; c2,c3 at row g+8) ----
    #pragma unroll
    for (int mt = 0; mt < 4; mt++) {
        int rbase = m0 + wm * 64 + mt * 16 + g;
        #pragma unroll
        for (int nt = 0; nt < 4; nt++) {
            int col = n0 + wn * 32 + nt * 8 + 2 * t;
            *(float2*)(Out + (size_t)rbase * N_DIM + col) =
                make_float2(acc[mt][nt][0], acc[mt][nt][1]);
            *(float2*)(Out + (size_t)(rbase + 8) * N_DIM + col) =
                make_float2(acc[mt][nt][2], acc[mt][nt][3]);
        }
    }
}

// ---------------------------------------------------------------------------
// Launch
// ---------------------------------------------------------------------------
extern "C" void kernel_launch(void* const* d_in, const int* in_sizes, int n_in,
                              void* d_out, int out_size) {
    const float* x   = (const float*)d_in[0];   // [4, 2048, 4096] f32
    const int*   gi  = (const int*)d_in[1];     // [4096, 4096] i32
    const float* lut = (const float*)d_in[2];   // [65536] f32
    const float* sc  = (const float*)d_in[3];   // [4096, 1] f32
    float* out = (float*)d_out;                 // [4, 2048, 4096] f32

    (void)in_sizes; (void)n_in; (void)out_size;

    ghost_dequant<<<(N_DIM * (size_t)K_DIM / 8) / 256, 256>>>((const int4*)gi, lut, sc);
    ghost_xconv<<<(M_DIM * (size_t)K_DIM / 8) / 256, 256>>>((const float4*)x);

    cudaFuncSetAttribute(ghost_gemm, cudaFuncAttributeMaxDynamicSharedMemorySize, SMEM_DYN);
    ghost_gemm<<<dim3(N_DIM / BN, M_DIM / BM), 256, SMEM_DYN>>>(out);
}

// round 4
// speedup vs baseline: 4.6427x; 1.3260x over previous
#include <cuda_runtime.h>
#include <cuda_fp16.h>
#include <cstdint>
#include <cstddef>

// GhostLinear: out = x @ (lut[gi]*scale)^T.  M=8192, N=4096, K=4096.
// R4: fp16 mma.m16n8k16 + ldmatrix; BK=64, 3-stage cp.async (96KB smem),
// 2 CTAs/SM; SW128 swizzle on 128B rows (chunk ^= row&7).

#define M_DIM 8192
#define N_DIM 4096
#define K_DIM 4096

#define BM 128
#define BN 128
#define BK 64
#define NSTAGES 3
#define NK (K_DIM / BK)                 // 64

#define TILE_BYTES (128 * 128)          // 128 rows x 64 halfs (128B)
#define STAGE_BYTES (2 * TILE_BYTES)    // A + B = 32768
#define SMEM_DYN (NSTAGES * STAGE_BYTES)  // 98304

// Scratch (device globals: allocation-free): W fp16 (32MB) + X fp16 (64MB)
__device__ __half g_Wh[(size_t)N_DIM * (size_t)K_DIM];
__device__ __half g_Xh[(size_t)M_DIM * (size_t)K_DIM];

__device__ __forceinline__ uint32_t smem_u32(const void* p) {
    uint32_t a;
    asm("{ .reg .u64 t; cvta.to.shared.u64 t, %1; cvt.u32.u64 %0, t; }"
        : "=r"(a) : "l"(p));
    return a;
}

#define CP_ASYNC16(smem, gmem) \
    asm volatile("cp.async.cg.shared.global [%0], [%1], 16;" :: "r"(smem), "l"(gmem) : "memory")
#define CP_COMMIT() asm volatile("cp.async.commit_group;" ::: "memory")
#define CP_WAIT(n)  asm volatile("cp.async.wait_group %0;" :: "n"(n) : "memory")

#define LDSM_X4(r0, r1, r2, r3, addr) \
    asm volatile("ldmatrix.sync.aligned.m8n8.x4.shared.b16 {%0,%1,%2,%3}, [%4];" \
                 : "=r"(r0), "=r"(r1), "=r"(r2), "=r"(r3) : "r"(addr))

__device__ __forceinline__ void mma_f16(float& c0, float& c1, float& c2, float& c3,
                                        uint32_t a0, uint32_t a1, uint32_t a2, uint32_t a3,
                                        uint32_t b0, uint32_t b1) {
    asm volatile(
        "mma.sync.aligned.m16n8k16.row.col.f32.f16.f16.f32 "
        "{%0,%1,%2,%3}, {%4,%5,%6,%7}, {%8,%9}, {%0,%1,%2,%3};"
        : "+f"(c0), "+f"(c1), "+f"(c2), "+f"(c3)
        : "r"(a0), "r"(a1), "r"(a2), "r"(a3), "r"(b0), "r"(b1));
}

// ---------------------------------------------------------------------------
// Prep kernels
// ---------------------------------------------------------------------------
__global__ void __launch_bounds__(256) ghost_dequant(const int4* __restrict__ gi,
                                                     const float* __restrict__ lut,
                                                     const float* __restrict__ scale) {
    unsigned i = blockIdx.x * 256u + threadIdx.x;      // 8-pack index
    int4 v0 = gi[2 * i];
    int4 v1 = gi[2 * i + 1];
    float s = __ldg(&scale[i >> 9]);
    __half2 h0 = __floats2half2_rn(__ldg(&lut[v0.x]) * s, __ldg(&lut[v0.y]) * s);
    __half2 h1 = __floats2half2_rn(__ldg(&lut[v0.z]) * s, __ldg(&lut[v0.w]) * s);
    __half2 h2 = __floats2half2_rn(__ldg(&lut[v1.x]) * s, __ldg(&lut[v1.y]) * s);
    __half2 h3 = __floats2half2_rn(__ldg(&lut[v1.z]) * s, __ldg(&lut[v1.w]) * s);
    uint4 w;
    w.x = *(uint32_t*)&h0; w.y = *(uint32_t*)&h1;
    w.z = *(uint32_t*)&h2; w.w = *(uint32_t*)&h3;
    reinterpret_cast<uint4*>(g_Wh)[i] = w;
}

__global__ void __launch_bounds__(256) ghost_xconv(const float4* __restrict__ X) {
    unsigned i = blockIdx.x * 256u + threadIdx.x;
    float4 f0 = X[2 * i];
    float4 f1 = X[2 * i + 1];
    __half2 h0 = __floats2half2_rn(f0.x, f0.y);
    __half2 h1 = __floats2half2_rn(f0.z, f0.w);
    __half2 h2 = __floats2half2_rn(f1.x, f1.y);
    __half2 h3 = __floats2half2_rn(f1.z, f1.w);
    uint4 w;
    w.x = *(uint32_t*)&h0; w.y = *(uint32_t*)&h1;
    w.z = *(uint32_t*)&h2; w.w = *(uint32_t*)&h3;
    reinterpret_cast<uint4*>(g_Xh)[i] = w;
}

// ---------------------------------------------------------------------------
// GEMM: Out[M,N] = Xh[M,K] * Wh[N,K]^T
// 256 threads = 8 warps (2m x 4n), warp tile 64x32, mma m16n8k16 f16->f32.
// smem row = 64 halfs (128B = 8 x 16B chunks); SW128 swizzle: chunk ^= (row&7).
// ---------------------------------------------------------------------------
__global__ void __launch_bounds__(256, 2) ghost_gemm(float* __restrict__ Out) {
    extern __shared__ char dynsmem[];

    const int tid = threadIdx.x;
    const int lane = tid & 31;
    const int wid = tid >> 5;
    const int wm = wid >> 2;              // 0..1
    const int wn = wid & 3;               // 0..3
    const int g = lane >> 2;              // 0..7
    const int t = lane & 3;               // 0..3

    const int n0 = blockIdx.x * BN;
    const int m0 = blockIdx.y * BM;

    const uint32_t sbase = smem_u32(dynsmem);

    // ---- cp.async geometry: 4 chunks/thread per tile per stage ----
    // chunk id = tid + 256*j : row = tid>>3 (+32j), c = tid&7 (same swizzle key all j)
    const int cprow = tid >> 3;                        // 0..31
    const int cpc = tid & 7;
    const uint32_t cpOff0 = (uint32_t)(cprow * 128 + ((cpc ^ (cprow & 7)) << 4));
    const __half* gAb = g_Xh + (size_t)(m0 + cprow) * K_DIM + cpc * 8;
    const __half* gBb = g_Wh + (size_t)(n0 + cprow) * K_DIM + cpc * 8;
    // chunk j: smem += j*4096 ; gmem += j*32*K_DIM

    // ---- prologue: fill 2 stages ----
    #pragma unroll
    for (int c = 0; c < NSTAGES - 1; c++) {
        uint32_t ab = sbase + c * STAGE_BYTES;
        uint32_t bb = ab + TILE_BYTES;
        int koff = c * BK;
        #pragma unroll
        for (int j = 0; j < 4; j++) {
            CP_ASYNC16(ab + cpOff0 + j * 4096, gAb + (size_t)j * 32 * K_DIM + koff);
            CP_ASYNC16(bb + cpOff0 + j * 4096, gBb + (size_t)j * 32 * K_DIM + koff);
        }
        CP_COMMIT();
    }

    // ---- ldmatrix per-thread address pieces ----
    const int q = lane >> 3;              // matrix slot 0..3
    const int r = lane & 7;               // row-within-matrix = swizzle key
    const uint32_t aRB = (uint32_t)(wm * 64 + (q & 1) * 8 + r) * 128;
    const uint32_t bRB = (uint32_t)(wn * 32 + (q >> 1) * 8 + r) * 128;
    const uint32_t aCQ = (uint32_t)(q >> 1);
    const uint32_t bCQ = (uint32_t)(q & 1);

    float acc[4][4][4];
    #pragma unroll
    for (int i = 0; i < 4; i++)
        #pragma unroll
        for (int j = 0; j < 4; j++)
            #pragma unroll
            for (int k2 = 0; k2 < 4; k2++) acc[i][j][k2] = 0.0f;

    #pragma unroll 1
    for (int kt = 0; kt < NK; kt++) {
        if (kt < NK - 1) CP_WAIT(1);
        else             CP_WAIT(0);
        __syncthreads();

        // prefetch stage kt+2 into the slot freed last iteration
        const int kc = kt + (NSTAGES - 1);
        if (kc < NK) {
            uint32_t ab = sbase + (kc % NSTAGES) * STAGE_BYTES;
            uint32_t bb = ab + TILE_BYTES;
            int koff = kc * BK;
            #pragma unroll
            for (int j = 0; j < 4; j++) {
                CP_ASYNC16(ab + cpOff0 + j * 4096, gAb + (size_t)j * 32 * K_DIM + koff);
                CP_ASYNC16(bb + cpOff0 + j * 4096, gBb + (size_t)j * 32 * K_DIM + koff);
            }
            CP_COMMIT();
        }

        const uint32_t aTile = sbase + (kt % NSTAGES) * STAGE_BYTES;
        const uint32_t bTile = aTile + TILE_BYTES;

        #pragma unroll
        for (int ks = 0; ks < 4; ks++) {              // four k16 steps per BK=64
            const uint32_t cA = ((uint32_t)(ks * 2) + aCQ) ^ (uint32_t)r;
            const uint32_t cB = ((uint32_t)(ks * 2) + bCQ) ^ (uint32_t)r;

            uint32_t a[4][4];
            #pragma unroll
            for (int mt = 0; mt < 4; mt++) {
                uint32_t addr = aTile + aRB + (uint32_t)(mt * 2048) + (cA << 4);
                LDSM_X4(a[mt][0], a[mt][1], a[mt][2], a[mt][3], addr);
            }
            uint32_t b[2][4];
            #pragma unroll
            for (int nt2 = 0; nt2 < 2; nt2++) {
                uint32_t addr = bTile + bRB + (uint32_t)(nt2 * 2048) + (cB << 4);
                LDSM_X4(b[nt2][0], b[nt2][1], b[nt2][2], b[nt2][3], addr);
            }

            #pragma unroll
            for (int mt = 0; mt < 4; mt++) {
                #pragma unroll
                for (int nt = 0; nt < 4; nt++) {
                    mma_f16(acc[mt][nt][0], acc[mt][nt][1], acc[mt][nt][2], acc[mt][nt][3],
                            a[mt][0], a[mt][1], a[mt][2], a[mt][3],
                            b[nt >> 1][2 * (nt & 1)], b[nt >> 1][2 * (nt & 1) + 1]);
                }
            }
        }
    }

    // ---- epilogue: direct float2 stores (c0,c1 at row g; c2,c3 at row g+8) ----
    #pragma unroll
    for (int mt = 0; mt < 4; mt++) {
        int rbase = m0 + wm * 64 + mt * 16 + g;
        #pragma unroll
        for (int nt = 0; nt < 4; nt++) {
            int col = n0 + wn * 32 + nt * 8 + 2 * t;
            *(float2*)(Out + (size_t)rbase * N_DIM + col) =
                make_float2(acc[mt][nt][0], acc[mt][nt][1]);
            *(float2*)(Out + (size_t)(rbase + 8) * N_DIM + col) =
                make_float2(acc[mt][nt][2], acc[mt][nt][3]);
        }
    }
}

// ---------------------------------------------------------------------------
// Launch
// ---------------------------------------------------------------------------
extern "C" void kernel_launch(void* const* d_in, const int* in_sizes, int n_in,
                              void* d_out, int out_size) {
    const float* x   = (const float*)d_in[0];   // [4, 2048, 4096] f32
    const int*   gi  = (const int*)d_in[1];     // [4096, 4096] i32
    const float* lut = (const float*)d_in[2];   // [65536] f32
    const float* sc  = (const float*)d_in[3];   // [4096, 1] f32
    float* out = (float*)d_out;                 // [4, 2048, 4096] f32

    (void)in_sizes; (void)n_in; (void)out_size;

    ghost_dequant<<<(N_DIM * (size_t)K_DIM / 8) / 256, 256>>>((const int4*)gi, lut, sc);
    ghost_xconv<<<(M_DIM * (size_t)K_DIM / 8) / 256, 256>>>((const float4*)x);

    cudaFuncSetAttribute(ghost_gemm, cudaFuncAttributeMaxDynamicSharedMemorySize, SMEM_DYN);
    ghost_gemm<<<dim3(N_DIM / BN, M_DIM / BM), 256, SMEM_DYN>>>(out);
}